// round 2
// baseline (speedup 1.0000x reference)
#include <cuda_runtime.h>
#include <math.h>

// StableMoEGate: logits = x @ W^T  (T=16384, H=4096, E=64)
// then softmax over E, top-2, renorm softmax over the two scores.
// Output pack: single float32 buffer: [2T scores][2T idx-as-float][1 aux=0]

#define Hdim 4096
#define Edim 64
#define KT   32
#define TM   64
#define XPAD 68   // padded row length (floats) for transposed smem tiles

__global__ __launch_bounds__(256) void moe_gate_kernel(
    const float* __restrict__ x,
    const float* __restrict__ W,
    float* __restrict__ out,
    int T)
{
    // smem: xs[KT][XPAD] @0, ws[KT][XPAD] @ KT*XPAD; logits [64][65] overlays after compute
    __shared__ float smem[2 * KT * XPAD];  // 2*32*68 = 4352 floats = 17.4 KB
    float* xs = smem;
    float* ws = smem + KT * XPAD;

    const int tid = threadIdx.x;
    const int m0  = blockIdx.x * TM;

    // compute-thread mapping: 16x16 grid of threads, 4x4 micro-tile each
    const int tx = tid & 15;   // expert group: experts tx*4 .. tx*4+3
    const int ty = tid >> 4;   // token  group: tokens  ty*4 .. ty*4+3

    // loader mapping: 512 float4 chunks per tile per matrix; thread does chunks tid, tid+256
    const int lm  = tid >> 3;  // row (token or expert) 0..31  (chunk2 adds +32)
    const int lk4 = tid & 7;   // which float4 within the 32-float row slice

    const float* xg = x + (size_t)(m0 + lm) * Hdim + lk4 * 4;
    const float* wg = W + (size_t)lm        * Hdim + lk4 * 4;
    const size_t rowskip = (size_t)32 * Hdim;

    float acc[4][4];
    #pragma unroll
    for (int i = 0; i < 4; i++)
        #pragma unroll
        for (int j = 0; j < 4; j++) acc[i][j] = 0.0f;

    // prefetch tile 0
    float4 px0 = *(const float4*)(xg);
    float4 px1 = *(const float4*)(xg + rowskip);
    float4 pw0 = *(const float4*)(wg);
    float4 pw1 = *(const float4*)(wg + rowskip);

    for (int kt = 0; kt < Hdim; kt += KT) {
        // store prefetched tile into transposed smem: xs[k][m], ws[k][e]
        #pragma unroll
        for (int j = 0; j < 4; j++) {
            int krow = (lk4 * 4 + j) * XPAD;
            xs[krow + lm]      = ((const float*)&px0)[j];
            xs[krow + lm + 32] = ((const float*)&px1)[j];
            ws[krow + lm]      = ((const float*)&pw0)[j];
            ws[krow + lm + 32] = ((const float*)&pw1)[j];
        }
        __syncthreads();

        // issue next tile's global loads (hidden under compute)
        if (kt + KT < Hdim) {
            const float* xp = xg + kt + KT;
            const float* wp = wg + kt + KT;
            px0 = *(const float4*)(xp);
            px1 = *(const float4*)(xp + rowskip);
            pw0 = *(const float4*)(wp);
            pw1 = *(const float4*)(wp + rowskip);
        }

        // compute: 32 k-steps, float4 LDS over tokens/experts (conflict-free)
        const float4* xs4 = (const float4*)xs;
        const float4* ws4 = (const float4*)ws;
        #pragma unroll
        for (int kk = 0; kk < KT; kk++) {
            float4 a = xs4[kk * (XPAD / 4) + ty];
            float4 b = ws4[kk * (XPAD / 4) + tx];
            float af[4] = {a.x, a.y, a.z, a.w};
            float bf[4] = {b.x, b.y, b.z, b.w};
            #pragma unroll
            for (int i = 0; i < 4; i++)
                #pragma unroll
                for (int j = 0; j < 4; j++)
                    acc[i][j] = fmaf(af[i], bf[j], acc[i][j]);
        }
        __syncthreads();
    }

    // ---- epilogue: write logits to smem [64 tokens][65], then per-token scan ----
    float* lg = smem;  // 64*65 = 4160 floats, fits in the 4352-float buffer
    #pragma unroll
    for (int i = 0; i < 4; i++)
        #pragma unroll
        for (int j = 0; j < 4; j++)
            lg[(ty * 4 + i) * 65 + (tx * 4 + j)] = acc[i][j];
    __syncthreads();

    if (tid < TM) {
        const float* row = lg + tid * 65;
        float best1 = -3.4e38f, best2 = -3.4e38f;
        int   i1 = 0, i2 = 0;
        #pragma unroll 8
        for (int e = 0; e < Edim; e++) {
            float l = row[e];
            if (l > best1) { best2 = best1; i2 = i1; best1 = l; i1 = e; }
            else if (l > best2) { best2 = l; i2 = e; }
        }
        float Z = 0.0f;
        #pragma unroll 8
        for (int e = 0; e < Edim; e++) Z += expf(row[e] - best1);
        float s1 = 1.0f / Z;                       // exp(best1-best1)/Z
        float s2 = expf(best2 - best1) / Z;
        // renorm: softmax over (s1, s2); s2 - s1 <= 0
        float p1 = 1.0f / (1.0f + expf(s2 - s1));
        float p2 = 1.0f - p1;

        int m = m0 + tid;
        out[2 * m + 0] = p1;
        out[2 * m + 1] = p2;
        // indices stored as FLOAT values (single-dtype output buffer)
        float* oi = out + 2 * T;
        oi[2 * m + 0] = (float)i1;
        oi[2 * m + 1] = (float)i2;
    }
    if (blockIdx.x == 0 && tid == 0) out[4 * T] = 0.0f;  // aux loss
}

extern "C" void kernel_launch(void* const* d_in, const int* in_sizes, int n_in,
                              void* d_out, int out_size)
{
    const float* x = (const float*)d_in[0];
    const float* W = (const float*)d_in[1];
    int T = in_sizes[0] / Hdim;     // 16384
    (void)n_in; (void)out_size;
    moe_gate_kernel<<<T / TM, 256>>>(x, W, (float*)d_out, T);
}

// round 4
// speedup vs baseline: 1.2048x; 1.2048x over previous
#include <cuda_runtime.h>
#include <math.h>
#include <stdint.h>

// StableMoEGate, SIMT fp32 with packed fma.rn.f32x2 (FFMA2) over the K dim.
// logits = x @ W^T (T=16384, H=4096, E=64); softmax; top-2; renorm softmax.
// Output: single f32 buffer [2T scores][2T idx-as-float][1 aux=0].

#define Hdim 4096
#define Edim 64
#define MT   64            // tokens per CTA
#define KT   32            // k per chunk
#define NCH  (Hdim / KT)   // 128 chunks

static __device__ __forceinline__ uint32_t smem_u32(const void* p) {
    uint32_t a;
    asm("{ .reg .u64 t; cvta.to.shared.u64 t, %1; cvt.u32.u64 %0, t; }" : "=r"(a) : "l"(p));
    return a;
}

__global__ __launch_bounds__(128) void moe_gate_f32x2_kernel(
    const float* __restrict__ x,
    const float* __restrict__ W,
    float* __restrict__ out,
    int T)
{
    // xs: [64 tok][32 k] @ float index 0      (2048 floats, swizzled 16B cols)
    // ws: [64 exp][32 k] @ float index 2048
    // lg overlay for epilogue: [64][66] = 4224 floats
    __shared__ float smem[4224];
    const uint32_t sbase = smem_u32(smem);
    const uint32_t xs_a = sbase;
    const uint32_t ws_a = sbase + 2048 * 4;

    const int tid = threadIdx.x;
    const int wid = tid >> 5;
    const int lid = tid & 31;
    const int m0  = blockIdx.x * MT;

    // compute mapping: warp grid 2 (token-rows) x 2 (expert-cols)
    const int wr = wid >> 1;          // 0..1 : tokens wr*32 + ...
    const int wc = wid & 1;           // 0..1 : experts wc*32 + ...
    const int lt = lid & 7;           // token lane  : tokens wr*32 + lt*4 + i
    const int le = lid >> 3;          // expert lane : experts wc*32 + le*8 + j

    // loader mapping: row = (tid>>3) + 16*pass (0..63), kchunk = tid&7
    const int lrow = tid >> 3;        // 0..15
    const int lk   = tid & 7;         // 0..7  (float4 within 32-k row)

    const float* xg = x + (size_t)(m0 + lrow) * Hdim + lk * 4;
    const float* wg = W + (size_t)lrow        * Hdim + lk * 4;
    const size_t rskip = (size_t)16 * Hdim;

    uint64_t acc[4][8];
    #pragma unroll
    for (int i = 0; i < 4; i++)
        #pragma unroll
        for (int j = 0; j < 8; j++) acc[i][j] = 0ull;

    // prefetch chunk 0
    float4 px[4], pw[4];
    #pragma unroll
    for (int p = 0; p < 4; p++) {
        px[p] = *(const float4*)(xg + p * rskip);
        pw[p] = *(const float4*)(wg + p * rskip);
    }

    for (int it = 0; it < NCH; it++) {
        // store prefetched tile, swizzled: float-index row*32 + 4*(kc ^ ((row>>2)&7))
        #pragma unroll
        for (int p = 0; p < 4; p++) {
            const int r  = lrow + 16 * p;
            const int sc = lk ^ ((r >> 2) & 7);
            *(float4*)(smem + r * 32 + 4 * sc)        = px[p];
            *(float4*)(smem + 2048 + r * 32 + 4 * sc) = pw[p];
        }
        __syncthreads();

        // prefetch next chunk
        if (it + 1 < NCH) {
            const int k1 = (it + 1) * KT;
            #pragma unroll
            for (int p = 0; p < 4; p++) {
                px[p] = *(const float4*)(xg + k1 + p * rskip);
                pw[p] = *(const float4*)(wg + k1 + p * rskip);
            }
        }

        // compute: 8 q-groups of 4 k each
        #pragma unroll
        for (int q = 0; q < 8; q++) {
            uint64_t xp0[4], xp1[4];
            #pragma unroll
            for (int i = 0; i < 4; i++) {
                const int tok = wr * 32 + lt * 4 + i;           // tok>>2 == 8*wr + lt
                const uint32_t xa = xs_a + (tok << 7) + ((q ^ lt) << 4);
                asm volatile("ld.shared.v2.u64 {%0,%1},[%2];"
                             : "=l"(xp0[i]), "=l"(xp1[i]) : "r"(xa));
            }
            #pragma unroll
            for (int j = 0; j < 8; j++) {
                const int e = wc * 32 + le * 8 + j;             // e>>2 == 8*wc + 2*le + (j>>2)
                const uint32_t wa = ws_a + (e << 7) + ((q ^ (2 * le + (j >> 2))) << 4);
                uint64_t w0, w1;
                asm volatile("ld.shared.v2.u64 {%0,%1},[%2];"
                             : "=l"(w0), "=l"(w1) : "r"(wa));
                #pragma unroll
                for (int i = 0; i < 4; i++) {
                    asm("fma.rn.f32x2 %0, %1, %2, %0;" : "+l"(acc[i][j]) : "l"(xp0[i]), "l"(w0));
                    asm("fma.rn.f32x2 %0, %1, %2, %0;" : "+l"(acc[i][j]) : "l"(xp1[i]), "l"(w1));
                }
            }
        }
        __syncthreads();
    }

    // ---- epilogue: reduce pairs, gather logits to smem [64][66] ----
    #pragma unroll
    for (int i = 0; i < 4; i++) {
        const int tok = wr * 32 + lt * 4 + i;
        #pragma unroll
        for (int j = 0; j < 8; j++) {
            const int e = wc * 32 + le * 8 + j;
            float lo, hi;
            asm("mov.b64 {%0,%1}, %2;" : "=f"(lo), "=f"(hi) : "l"(acc[i][j]));
            smem[tok * 66 + e] = lo + hi;
        }
    }
    __syncthreads();

    if (tid < MT) {
        const float* row = smem + tid * 66;
        float best1 = -3.4e38f, best2 = -3.4e38f;
        int i1 = 0, i2 = 0;
        #pragma unroll 8
        for (int e = 0; e < Edim; e++) {
            const float l = row[e];
            if (l > best1) { best2 = best1; i2 = i1; best1 = l; i1 = e; }
            else if (l > best2) { best2 = l; i2 = e; }
        }
        float Z = 0.0f;
        #pragma unroll 8
        for (int e = 0; e < Edim; e++) Z += expf(row[e] - best1);
        const float s1 = 1.0f / Z;
        const float s2 = expf(best2 - best1) / Z;
        const float p1 = 1.0f / (1.0f + expf(s2 - s1));
        const float p2 = 1.0f - p1;

        const int m = m0 + tid;
        out[2 * m + 0] = p1;
        out[2 * m + 1] = p2;
        float* oi = out + 2 * T;              // indices stored as float values
        oi[2 * m + 0] = (float)i1;
        oi[2 * m + 1] = (float)i2;
    }
    if (blockIdx.x == 0 && tid == 0) out[4 * T] = 0.0f;
}

extern "C" void kernel_launch(void* const* d_in, const int* in_sizes, int n_in,
                              void* d_out, int out_size)
{
    const float* x = (const float*)d_in[0];
    const float* W = (const float*)d_in[1];
    int T = in_sizes[0] / Hdim;   // 16384
    (void)n_in; (void)out_size;
    moe_gate_f32x2_kernel<<<T / MT, 128>>>(x, W, (float*)d_out, T);
}